// round 8
// baseline (speedup 1.0000x reference)
#include <cuda_runtime.h>
#include <math.h>

// ---------------- problem constants ----------------
#define NN 20000
#define EE 200000
#define HSZ (1u<<19)
#define HMASK (HSZ-1u)
#define NEG_ORD (-2139095041)

// ---------------- scratch ----------------
__device__ float    g_EB[EE*768];
__device__ float    g_EC[EE*768];
__device__ float    g_Xa[NN*768];
__device__ float    g_Xd[NN*768];
__device__ float    g_hbuf[EE*768];
__device__ float    g_upe[EE*256];
__device__ float    g_Qn[NN*256];
__device__ float    g_Vn[NN*256];
__device__ float    g_Ke[EE*256];
__device__ int      g_aggI[NN*256];
__device__ float    g_agg[NN*256];
__device__ float    g_cat[NN*512];
__device__ float    g_hn[NN*512];
__device__ float    g_upn[NN*256];
__device__ float    g_twin[NN*512];
__device__ float    g_osum[NN*256];
__device__ float    g_isum[NN*256];
__device__ int      g_ocnt[NN];
__device__ int      g_icnt[NN];
__device__ int      g_rev[EE];
__device__ unsigned g_hkey[HSZ];
__device__ int      g_hval[HSZ];
// pre-rounded (tf32) operand copies
__device__ float    g_xr[NN*256];
__device__ float    g_ear[EE*256];
__device__ float    g_We1r[768*1024];
__device__ float    g_We2r[256*768];
__device__ float    g_Wqr[256*256];
__device__ float    g_Wkr[256*256];
__device__ float    g_Wvr[256*256];
__device__ float    g_Wn1r[512*512];
__device__ float    g_Wn2r[256*512];
__device__ float    g_Wear[256*512];

__device__ __forceinline__ int f2oi(float f){
    int i = __float_as_int(f);
    return i >= 0 ? i : i ^ 0x7FFFFFFF;
}
__device__ __forceinline__ float oi2f(int i){
    return __int_as_float(i >= 0 ? i : i ^ 0x7FFFFFFF);
}
__device__ __forceinline__ unsigned f2tf32(float f){
    unsigned u;
    asm("cvt.rna.tf32.f32 %0, %1;" : "=r"(u) : "f"(f));
    return u;
}
__device__ __forceinline__ float rtf(float f){ return __uint_as_float(f2tf32(f)); }

// ---------------- init ----------------
__global__ void k_init(int N){
    int i = blockIdx.x*blockDim.x + threadIdx.x;
    if(i < (int)HSZ) g_hkey[i] = 0xFFFFFFFFu;
    if(i < N*256){ g_aggI[i] = NEG_ORD; g_osum[i] = 0.f; g_isum[i] = 0.f; }
    if(i < N){ g_ocnt[i] = 0; g_icnt[i] = 0; }
}

// ---------------- tf32 pre-rounding pass ----------------
__global__ void k_round4(const float4* __restrict__ src, float4* __restrict__ dst, int n4){
    int i = blockIdx.x*blockDim.x + threadIdx.x;
    if(i >= n4) return;
    float4 v = src[i];
    v.x = rtf(v.x); v.y = rtf(v.y); v.z = rtf(v.z); v.w = rtf(v.w);
    dst[i] = v;
}

// ---------------- reverse-edge hash table ----------------
__global__ void k_hash_insert(const int* __restrict__ ei, int E, int N){
    int e = blockIdx.x*blockDim.x + threadIdx.x;
    if(e >= E) return;
    unsigned key = (unsigned)ei[e] * (unsigned)N + (unsigned)ei[E+e];
    unsigned slot = ((key * 2654435761u) >> 13) & HMASK;
    while(true){
        unsigned prev = atomicCAS(&g_hkey[slot], 0xFFFFFFFFu, key);
        if(prev == 0xFFFFFFFFu){ g_hval[slot] = e; break; }
        slot = (slot + 1u) & HMASK;
    }
}

__global__ void k_rev(const int* __restrict__ ei, int E, int N){
    int e = blockIdx.x*blockDim.x + threadIdx.x;
    if(e >= E) return;
    unsigned rkey = (unsigned)ei[E+e] * (unsigned)N + (unsigned)ei[e];
    unsigned slot = ((rkey * 2654435761u) >> 13) & HMASK;
    int r = -1;
    while(true){
        unsigned kk = g_hkey[slot];
        if(kk == rkey){ r = g_hval[slot]; break; }
        if(kk == 0xFFFFFFFFu) break;
        slot = (slot + 1u) & HMASK;
    }
    g_rev[e] = r;
}

// ---- tf32 TC GEMM: 128x128 block, 4 warps (64x64 tiles), cp.async --------
#define RS 20                 // smem row stride (words): 8x20 mod 32 distinct quads
#define TW (128*RS)           // words per tile per stage
#define STAGES 4
#define SMEM_BYTES (STAGES*2*TW*4)

__device__ __forceinline__ void mma_tf32(float c[4], const unsigned a[4], const unsigned b[2]){
    asm volatile(
        "mma.sync.aligned.m16n8k8.row.col.f32.tf32.tf32.f32 "
        "{%0,%1,%2,%3}, {%4,%5,%6,%7}, {%8,%9}, {%0,%1,%2,%3};"
        : "+f"(c[0]), "+f"(c[1]), "+f"(c[2]), "+f"(c[3])
        : "r"(a[0]), "r"(a[1]), "r"(a[2]), "r"(a[3]), "r"(b[0]), "r"(b[1]));
}
__device__ __forceinline__ void ldsm4(unsigned &r0, unsigned &r1, unsigned &r2, unsigned &r3,
                                      unsigned addr){
    asm volatile("ldmatrix.sync.aligned.m8n8.x4.shared.b16 {%0,%1,%2,%3}, [%4];"
        : "=r"(r0), "=r"(r1), "=r"(r2), "=r"(r3) : "r"(addr));
}
__device__ __forceinline__ void cp16(unsigned daddr, const void* gptr, int srcsize){
    asm volatile("cp.async.cg.shared.global [%0], [%1], 16, %2;"
        :: "r"(daddr), "l"(gptr), "r"(srcsize));
}
__device__ __forceinline__ void cp_commit(){
    asm volatile("cp.async.commit_group;" ::: "memory");
}
__device__ __forceinline__ void cp_wait2(){
    asm volatile("cp.async.wait_group 2;" ::: "memory");
}

__device__ __forceinline__ void emit(float v, size_t idx,
                                     float* C, float* C2, const float* aux, int mode){
    if(mode == 0)      C[idx] = v;
    else if(mode == 1) C[idx] = rtf(fmaxf(v, 0.f));   // hn: GEMM input downstream
    else if(mode == 2){ C[idx] = v; C2[idx] = fmaxf(v, 0.f); }
    else { float s = 1.f/(1.f + __expf(-v)); C[idx] = fmaxf(aux[idx], 0.f) * s; }
}

__global__ void __launch_bounds__(128, 2)
k_tgemm(int M, int Ncol, int K,
        const float* __restrict__ A, int lda,
        const float* __restrict__ W, int ldw,
        const float* __restrict__ bias,
        float* __restrict__ C, int ldc,
        float* __restrict__ C2, const float* __restrict__ aux,
        int mode)
{
    extern __shared__ unsigned smem_u[];
    unsigned* sA = smem_u;               // [STAGES][TW]
    unsigned* sB = smem_u + STAGES*TW;   // [STAGES][TW]

    const int tid  = threadIdx.x;
    const int lane = tid & 31;
    const int warp = tid >> 5;           // 0..3
    const int tg   = lane & 3;
    const int g    = lane >> 2;
    const int bm   = blockIdx.y * 128;
    const int bn   = blockIdx.x * 128;
    const int mw   = (warp >> 1) * 64;   // 0 or 64
    const int nw   = (warp & 1) * 64;    // 0 or 64

    // copy coords: 4 x 16B chunks each for A and B per thread (128 threads)
    int cR[4], cK[4];
    #pragma unroll
    for(int i=0;i<4;i++){
        int f4 = i*128 + tid;
        cR[i] = f4 >> 2; cK[i] = (f4 & 3) << 2;
    }

    const unsigned sAaddr = (unsigned)__cvta_generic_to_shared(sA);
    const unsigned sBaddr = (unsigned)__cvta_generic_to_shared(sB);

    auto issue = [&](int k0, int buf){
        #pragma unroll
        for(int i=0;i<4;i++){
            int gm = bm + cR[i];
            int rowA = gm < M ? gm : (M-1);
            cp16(sAaddr + (unsigned)((buf*TW + cR[i]*RS + cK[i])*4),
                 A + (size_t)rowA*lda + k0 + cK[i], gm < M ? 16 : 0);
            cp16(sBaddr + (unsigned)((buf*TW + cR[i]*RS + cK[i])*4),
                 W + (size_t)(bn + cR[i])*ldw + k0 + cK[i], 16);
        }
        cp_commit();
    };

    // ldmatrix addressing
    const int lr = lane & 15;
    const int lc = (lane >> 4) << 2;
    unsigned aOff[4], bOff[4];
    #pragma unroll
    for(int mi=0;mi<4;mi++)   aOff[mi]  = ((mw + mi*16  + lr)*RS + lc) * 4u;
    #pragma unroll
    for(int ni2=0;ni2<4;ni2++) bOff[ni2] = ((nw + ni2*16 + lr)*RS + lc) * 4u;

    float acc[4][8][4];
    #pragma unroll
    for(int mi=0;mi<4;mi++)
        #pragma unroll
        for(int ni=0;ni<8;ni++)
            #pragma unroll
            for(int t=0;t<4;t++) acc[mi][ni][t] = 0.f;

    issue(0, 0); issue(16, 1); issue(32, 2);

    int buf = 0;
    for(int k0=0;k0<K;k0+=16){
        cp_wait2();
        __syncthreads();

        int knext = k0 + 48;
        if(knext < K) issue(knext, (buf + 3) & 3);
        else          cp_commit();

        const unsigned aBase = sAaddr + (unsigned)(buf*TW*4);
        const unsigned bBase = sBaddr + (unsigned)(buf*TW*4);
        #pragma unroll
        for(int ks=0;ks<16;ks+=8){
            unsigned af[4][4], bf[8][2];
            #pragma unroll
            for(int mi=0;mi<4;mi++)
                ldsm4(af[mi][0], af[mi][1], af[mi][2], af[mi][3],
                      aBase + aOff[mi] + ks*4u);
            #pragma unroll
            for(int ni2=0;ni2<4;ni2++){
                unsigned r0,r1,r2,r3;
                ldsm4(r0, r1, r2, r3, bBase + bOff[ni2] + ks*4u);
                bf[ni2*2+0][0] = r0; bf[ni2*2+0][1] = r2;
                bf[ni2*2+1][0] = r1; bf[ni2*2+1][1] = r3;
            }
            #pragma unroll
            for(int mi=0;mi<4;mi++)
                #pragma unroll
                for(int ni=0;ni<8;ni++)
                    mma_tf32(acc[mi][ni], af[mi], bf[ni]);
        }
        buf = (buf + 1) & 3;
    }

    // ---- epilogue
    #pragma unroll
    for(int mi=0;mi<4;mi++){
        int row0 = bm + mw + mi*16 + g;
        int row1 = row0 + 8;
        #pragma unroll
        for(int ni=0;ni<8;ni++){
            int col = bn + nw + ni*8 + tg*2;
            float b0 = bias ? bias[col]   : 0.f;
            float b1 = bias ? bias[col+1] : 0.f;
            if(row0 < M){
                size_t i0 = (size_t)row0*ldc + col;
                emit(acc[mi][ni][0] + b0, i0,   C, C2, aux, mode);
                emit(acc[mi][ni][1] + b1, i0+1, C, C2, aux, mode);
            }
            if(row1 < M){
                size_t i1 = (size_t)row1*ldc + col;
                emit(acc[mi][ni][2] + b0, i1,   C, C2, aux, mode);
                emit(acc[mi][ni][3] + b1, i1+1, C, C2, aux, mode);
            }
        }
    }
}

// ---------------- combine: h = relu(Xa[row] + EB + EC[rev] + Xd[col] + be1)
// output rounded to tf32 grid (it feeds the next GEMM)
__global__ void k_combine(const int* __restrict__ ei,
                          const float* __restrict__ be1, int E){
    long long gid = (long long)blockIdx.x*blockDim.x + threadIdx.x;
    if(gid >= (long long)E*192) return;
    int e = (int)(gid/192);
    int q = (int)(gid%192);
    int j = q*4;
    int r  = ei[e], c = ei[E+e], rv = g_rev[e];
    float4 v  = *(const float4*)(g_EB  + (size_t)e*768 + j);
    float4 xa = *(const float4*)(g_Xa  + (size_t)r*768 + j);
    float4 xd = *(const float4*)(g_Xd  + (size_t)c*768 + j);
    float4 b  = *(const float4*)(be1 + j);
    float4 o;
    o.x = v.x + xa.x + xd.x + b.x;
    o.y = v.y + xa.y + xd.y + b.y;
    o.z = v.z + xa.z + xd.z + b.z;
    o.w = v.w + xa.w + xd.w + b.w;
    if(rv >= 0){
        float4 ec = *(const float4*)(g_EC + (size_t)rv*768 + j);
        o.x += ec.x; o.y += ec.y; o.z += ec.z; o.w += ec.w;
    }
    o.x = rtf(fmaxf(o.x, 0.f)); o.y = rtf(fmaxf(o.y, 0.f));
    o.z = rtf(fmaxf(o.z, 0.f)); o.w = rtf(fmaxf(o.w, 0.f));
    *(float4*)(g_hbuf + (size_t)e*768 + j) = o;
}

// ---------------- fused attention MLP + softmax + weighted + scatter-max
__global__ void __launch_bounds__(256)
k_attn(const int* __restrict__ ei,
       const float* __restrict__ Wa1, const float* __restrict__ ba1,
       const float* __restrict__ Wa2, const float* __restrict__ ba2,
       float* __restrict__ out_prob, int E)
{
    __shared__ float4 sW1[1024];
    __shared__ float4 sW2[512];
    __shared__ float  sb1[64], sb2[32];
    for(int i=threadIdx.x;i<1024;i+=256) sW1[i] = ((const float4*)Wa1)[i];
    for(int i=threadIdx.x;i<512; i+=256) sW2[i] = ((const float4*)Wa2)[i];
    if(threadIdx.x < 64) sb1[threadIdx.x] = ba1[threadIdx.x];
    if(threadIdx.x < 32) sb2[threadIdx.x] = ba2[threadIdx.x];
    __syncthreads();

    long long gid = (long long)blockIdx.x*256 + threadIdx.x;
    if(gid >= (long long)E*8) return;
    int e = (int)(gid >> 3);
    int h = (int)(gid & 7);
    int r = ei[e], c = ei[E+e];

    float ain[64];
    const float* qrow = g_Qn + (size_t)r*256 + h;
    const float* krow = g_Ke + (size_t)e*256 + h;
    #pragma unroll
    for(int i=0;i<32;i++) ain[i]    = qrow[i*8];
    #pragma unroll
    for(int i=0;i<32;i++) ain[32+i] = krow[i*8];

    float att[32];
    #pragma unroll
    for(int p=0;p<32;p++) att[p] = sb2[p];

    #pragma unroll 1
    for(int o4=0;o4<16;o4++){
        float a1v[4];
        #pragma unroll
        for(int s=0;s<4;s++){
            int o = o4*4 + s;
            float a = sb1[o];
            #pragma unroll
            for(int c4=0;c4<16;c4++){
                float4 w = sW1[o*16 + c4];
                a += w.x*ain[c4*4+0] + w.y*ain[c4*4+1]
                   + w.z*ain[c4*4+2] + w.w*ain[c4*4+3];
            }
            a1v[s] = fmaxf(a, 0.f);
        }
        #pragma unroll
        for(int p=0;p<32;p++){
            float4 w = sW2[p*16 + o4];
            att[p] += w.x*a1v[0] + w.y*a1v[1] + w.z*a1v[2] + w.w*a1v[3];
        }
    }

    const float invT = 0.17677669529663687f;
    float mx = att[0];
    #pragma unroll
    for(int p=1;p<32;p++) mx = fmaxf(mx, att[p]);
    float sum = 0.f;
    #pragma unroll
    for(int p=0;p<32;p++){ att[p] = __expf((att[p]-mx)*invT); sum += att[p]; }
    float inv = 1.f/sum;

    float* pp = out_prob + (size_t)e*256 + h;
    const float* vrow = g_Vn + (size_t)c*256 + h;
    int* ar = g_aggI + r*256 + h;
    #pragma unroll
    for(int p=0;p<32;p++){
        float pr = att[p]*inv;
        pp[p*8] = pr;
        float w = pr * vrow[p*8];
        atomicMax(ar + p*8, f2oi(w));
    }
}

// ---------------- small elementwise kernels ----------------
__global__ void k_agg_final(int N){
    int i = blockIdx.x*blockDim.x + threadIdx.x;
    if(i >= N*256) return;
    float v = oi2f(g_aggI[i]);
    g_agg[i] = isfinite(v) ? v : 0.f;
}

__global__ void k_concat(const float* __restrict__ x, int N){
    int i = blockIdx.x*blockDim.x + threadIdx.x;
    if(i >= N*512) return;
    int n = i >> 9, j = i & 511;
    float v = (j < 256) ? x[(size_t)n*256 + j] : g_agg[(size_t)n*256 + j - 256];
    g_cat[i] = rtf(v);
}

__global__ void k_counts(const int* __restrict__ ei, int E){
    int e = blockIdx.x*blockDim.x + threadIdx.x;
    if(e >= E) return;
    atomicAdd(&g_ocnt[ei[e]],   1);
    atomicAdd(&g_icnt[ei[E+e]], 1);
}

__global__ void k_twin_scatter(const int* __restrict__ ei, int E){
    long long gid = (long long)blockIdx.x*blockDim.x + threadIdx.x;
    if(gid >= (long long)E*64) return;
    int e  = (int)(gid >> 6);
    int j4 = (int)(gid & 63);
    int r = ei[e], c = ei[E+e];
    float4 u = *(const float4*)(g_upe + (size_t)e*256 + j4*4);
    int base = j4*4;
    atomicAdd(&g_osum[r*256+base+0], u.x);
    atomicAdd(&g_osum[r*256+base+1], u.y);
    atomicAdd(&g_osum[r*256+base+2], u.z);
    atomicAdd(&g_osum[r*256+base+3], u.w);
    atomicAdd(&g_isum[c*256+base+0], u.x);
    atomicAdd(&g_isum[c*256+base+1], u.y);
    atomicAdd(&g_isum[c*256+base+2], u.z);
    atomicAdd(&g_isum[c*256+base+3], u.w);
}

__global__ void k_twin_final(int N){
    int i = blockIdx.x*blockDim.x + threadIdx.x;
    if(i >= N*512) return;
    int n = i >> 9, j = i & 511;
    float v;
    if(j < 256) v = g_osum[n*256 + j]       / fmaxf((float)g_ocnt[n], 1.f);
    else        v = g_isum[n*256 + j - 256] / fmaxf((float)g_icnt[n], 1.f);
    g_twin[i] = rtf(v);
}

// ---------------- launcher ----------------
extern "C" void kernel_launch(void* const* d_in, const int* in_sizes, int n_in,
                              void* d_out, int out_size)
{
    const float* x   = (const float*)d_in[0];
    const float* ea  = (const float*)d_in[1];
    const float* Wq  = (const float*)d_in[2];
    const float* bq  = (const float*)d_in[3];
    const float* Wk  = (const float*)d_in[4];
    const float* bk  = (const float*)d_in[5];
    const float* Wv  = (const float*)d_in[6];
    const float* bv  = (const float*)d_in[7];
    const float* We1 = (const float*)d_in[8];
    const float* be1 = (const float*)d_in[9];
    const float* We2 = (const float*)d_in[10];
    const float* be2 = (const float*)d_in[11];
    const float* Wea = (const float*)d_in[12];
    const float* bea = (const float*)d_in[13];
    const float* Wn1 = (const float*)d_in[14];
    const float* bn1 = (const float*)d_in[15];
    const float* Wn2 = (const float*)d_in[16];
    const float* bn2 = (const float*)d_in[17];
    const float* Wa1 = (const float*)d_in[18];
    const float* ba1 = (const float*)d_in[19];
    const float* Wa2 = (const float*)d_in[20];
    const float* ba2 = (const float*)d_in[21];
    const int*   ei  = (const int*)  d_in[22];

    const int N = in_sizes[0]/256;
    const int E = in_sizes[1]/256;

    float* out      = (float*)d_out;
    float* out_node = out;
    float* out_edge = out + (size_t)N*256;
    float* out_prob = out_edge + (size_t)E*256;

    void* p;
    #define GSYM(v, s) float* v; cudaGetSymbolAddress(&p, s); v = (float*)p;
    GSYM(pXa,  g_Xa)  GSYM(pXd,  g_Xd)  GSYM(pEB, g_EB) GSYM(pEC, g_EC)
    GSYM(pH,   g_hbuf) GSYM(pUPE, g_upe)
    GSYM(pQ,   g_Qn)  GSYM(pV,   g_Vn)  GSYM(pK,  g_Ke)
    GSYM(pCat, g_cat) GSYM(pHn,  g_hn)  GSYM(pUpn, g_upn) GSYM(pTwin, g_twin)
    GSYM(pXr,  g_xr)  GSYM(pEar, g_ear)
    GSYM(pWe1r, g_We1r) GSYM(pWe2r, g_We2r)
    GSYM(pWqr, g_Wqr) GSYM(pWkr, g_Wkr) GSYM(pWvr, g_Wvr)
    GSYM(pWn1r, g_Wn1r) GSYM(pWn2r, g_Wn2r) GSYM(pWear, g_Wear)
    #undef GSYM

    cudaFuncSetAttribute(k_tgemm, cudaFuncAttributeMaxDynamicSharedMemorySize, SMEM_BYTES);

    // pre-round all GEMM operands to the tf32 grid
    auto RND = [&](const float* src, float* dst, int n){
        k_round4<<<(n/4 + 255)/256, 256>>>((const float4*)src, (float4*)dst, n/4);
    };
    RND(x,   pXr,   N*256);
    RND(ea,  pEar,  E*256);
    RND(We1, pWe1r, 768*1024);
    RND(We2, pWe2r, 256*768);
    RND(Wq,  pWqr,  256*256);
    RND(Wk,  pWkr,  256*256);
    RND(Wv,  pWvr,  256*256);
    RND(Wn1, pWn1r, 512*512);
    RND(Wn2, pWn2r, 256*512);
    RND(Wea, pWear, 256*512);

    k_init<<<(NN*256+255)/256, 256>>>(N);
    k_hash_insert<<<(E+255)/256, 256>>>(ei, E, N);
    k_rev<<<(E+255)/256, 256>>>(ei, E, N);

    auto GEMM = [&](int M, int Nc, int K, const float* A, int lda,
                    const float* W, int ldw, const float* bias,
                    float* C, int ldc, float* C2, const float* aux, int mode){
        dim3 g(Nc/128, (M+127)/128);
        k_tgemm<<<g, 128, SMEM_BYTES>>>(M, Nc, K, A, lda, W, ldw, bias, C, ldc, C2, aux, mode);
    };

    // edge-update MLP, factored by We1 column blocks
    GEMM(N, 768, 256, pXr,  256, pWe1r + 0,   1024, nullptr, pXa, 768, nullptr, nullptr, 0);
    GEMM(N, 768, 256, pXr,  256, pWe1r + 768, 1024, nullptr, pXd, 768, nullptr, nullptr, 0);
    GEMM(E, 768, 256, pEar, 256, pWe1r + 256, 1024, nullptr, pEB, 768, nullptr, nullptr, 0);
    GEMM(E, 768, 256, pEar, 256, pWe1r + 512, 1024, nullptr, pEC, 768, nullptr, nullptr, 0);
    k_combine<<<(int)(((long long)E*192 + 255)/256), 256>>>(ei, be1, E);
    GEMM(E, 256, 768, pH, 768, pWe2r, 768, be2, pUPE, 256, out_edge, nullptr, 2);

    // q/v per node, k per edge
    GEMM(N, 256, 256, pXr,  256, pWqr, 256, bq, pQ, 256, nullptr, nullptr, 0);
    GEMM(N, 256, 256, pXr,  256, pWvr, 256, bv, pV, 256, nullptr, nullptr, 0);
    GEMM(E, 256, 256, pEar, 256, pWkr, 256, bk, pK, 256, nullptr, nullptr, 0);

    // attention + scatter-max aggregation
    k_attn<<<(int)(((long long)E*8 + 255)/256), 256>>>(ei, Wa1, ba1, Wa2, ba2, out_prob, E);
    k_agg_final<<<(N*256+255)/256, 256>>>(N);

    // node update MLP
    k_concat<<<(N*512+255)/256, 256>>>(x, N);
    GEMM(N, 512, 512, pCat, 512, pWn1r, 512, bn1, pHn,  512, nullptr, nullptr, 1);
    GEMM(N, 256, 512, pHn,  512, pWn2r, 512, bn2, pUpn, 256, nullptr, nullptr, 0);

    // twin aggregation + gated output
    k_counts<<<(E+255)/256, 256>>>(ei, E);
    k_twin_scatter<<<(int)(((long long)E*64 + 255)/256), 256>>>(ei, E);
    k_twin_final<<<(N*512+255)/256, 256>>>(N);
    GEMM(N, 256, 512, pTwin, 512, pWear, 512, bea, out_node, 256, nullptr, pUpn, 3);
}

// round 10
// speedup vs baseline: 1.4295x; 1.4295x over previous
#include <cuda_runtime.h>
#include <cuda_fp16.h>
#include <math.h>
#include <stdint.h>

// ---------------- problem constants ----------------
#define NN 20000
#define EE 200000
#define HSZ (1u<<19)
#define HMASK (HSZ-1u)
#define NEG_ORD (-2139095041)

// ---------------- scratch ----------------
__device__ float    g_EB[EE*768];
__device__ float    g_EC[EE*768];
__device__ float    g_Xa[NN*768];
__device__ float    g_Xd[NN*768];
__device__ float    g_upe[EE*256];
__device__ float    g_Qn[NN*256];
__device__ float    g_Vn[NN*256];
__device__ float    g_Ke[EE*256];
__device__ int      g_aggI[NN*256];
__device__ float    g_agg[NN*256];
__device__ float    g_upn[NN*256];
__device__ float    g_osum[NN*256];
__device__ float    g_isum[NN*256];
__device__ int      g_ocnt[NN];
__device__ int      g_icnt[NN];
__device__ int      g_rev[EE];
__device__ unsigned g_hkey[HSZ];
__device__ int      g_hval[HSZ];
// half (fp16) GEMM operand buffers
__device__ __half   g_xr[NN*256];
__device__ __half   g_ear[EE*256];
__device__ __half   g_hbuf[EE*768];
__device__ __half   g_cat[NN*512];
__device__ __half   g_hn[NN*512];
__device__ __half   g_twin[NN*512];
__device__ __half   g_We1h[768*1024];
__device__ __half   g_We2h[256*768];
__device__ __half   g_Wqh[256*256];
__device__ __half   g_Wkh[256*256];
__device__ __half   g_Wvh[256*256];
__device__ __half   g_Wn1h[512*512];
__device__ __half   g_Wn2h[256*512];
__device__ __half   g_Weah[256*512];

__device__ __forceinline__ int f2oi(float f){
    int i = __float_as_int(f);
    return i >= 0 ? i : i ^ 0x7FFFFFFF;
}
__device__ __forceinline__ float oi2f(int i){
    return __int_as_float(i >= 0 ? i : i ^ 0x7FFFFFFF);
}

// ---------------- init ----------------
__global__ void k_init(int N){
    int i = blockIdx.x*blockDim.x + threadIdx.x;
    if(i < (int)HSZ) g_hkey[i] = 0xFFFFFFFFu;
    if(i < N*256){ g_aggI[i] = NEG_ORD; g_osum[i] = 0.f; g_isum[i] = 0.f; }
    if(i < N){ g_ocnt[i] = 0; g_icnt[i] = 0; }
}

// ---------------- fp32 -> fp16 convert pass ----------------
__global__ void k_tohalf(const float4* __restrict__ src, uint2* __restrict__ dst, int n4){
    int i = blockIdx.x*blockDim.x + threadIdx.x;
    if(i >= n4) return;
    float4 v = src[i];
    __half2 h0 = __floats2half2_rn(v.x, v.y);
    __half2 h1 = __floats2half2_rn(v.z, v.w);
    dst[i] = make_uint2(*(unsigned*)&h0, *(unsigned*)&h1);
}

// ---------------- reverse-edge hash table ----------------
__global__ void k_hash_insert(const int* __restrict__ ei, int E, int N){
    int e = blockIdx.x*blockDim.x + threadIdx.x;
    if(e >= E) return;
    unsigned key = (unsigned)ei[e] * (unsigned)N + (unsigned)ei[E+e];
    unsigned slot = ((key * 2654435761u) >> 13) & HMASK;
    while(true){
        unsigned prev = atomicCAS(&g_hkey[slot], 0xFFFFFFFFu, key);
        if(prev == 0xFFFFFFFFu){ g_hval[slot] = e; break; }
        slot = (slot + 1u) & HMASK;
    }
}

__global__ void k_rev(const int* __restrict__ ei, int E, int N){
    int e = blockIdx.x*blockDim.x + threadIdx.x;
    if(e >= E) return;
    unsigned rkey = (unsigned)ei[E+e] * (unsigned)N + (unsigned)ei[e];
    unsigned slot = ((rkey * 2654435761u) >> 13) & HMASK;
    int r = -1;
    while(true){
        unsigned kk = g_hkey[slot];
        if(kk == rkey){ r = g_hval[slot]; break; }
        if(kk == 0xFFFFFFFFu) break;
        slot = (slot + 1u) & HMASK;
    }
    g_rev[e] = r;
}

// ---- fp16 TC GEMM: 128x128 block, warp tile 64x32, cp.async 4-stage ------
// smem rows: 32 halfs payload (64B), stride 40 halfs (80B): 5*16B odd -> conflict-free
#define RSH 40
#define TWB (128*RSH*2)       // bytes per tile per stage (10240)
#define STAGES 4
#define SMEM_BYTES (STAGES*2*TWB)

__device__ __forceinline__ void mma_f16(float c[4], const unsigned a[4], const unsigned b[2]){
    asm volatile(
        "mma.sync.aligned.m16n8k16.row.col.f32.f16.f16.f32 "
        "{%0,%1,%2,%3}, {%4,%5,%6,%7}, {%8,%9}, {%0,%1,%2,%3};"
        : "+f"(c[0]), "+f"(c[1]), "+f"(c[2]), "+f"(c[3])
        : "r"(a[0]), "r"(a[1]), "r"(a[2]), "r"(a[3]), "r"(b[0]), "r"(b[1]));
}
__device__ __forceinline__ void ldsm4(unsigned &r0, unsigned &r1, unsigned &r2, unsigned &r3,
                                      unsigned addr){
    asm volatile("ldmatrix.sync.aligned.m8n8.x4.shared.b16 {%0,%1,%2,%3}, [%4];"
        : "=r"(r0), "=r"(r1), "=r"(r2), "=r"(r3) : "r"(addr));
}
__device__ __forceinline__ void cp16(unsigned daddr, const void* gptr, int srcsize){
    asm volatile("cp.async.cg.shared.global [%0], [%1], 16, %2;"
        :: "r"(daddr), "l"(gptr), "r"(srcsize));
}
__device__ __forceinline__ void cp_commit(){
    asm volatile("cp.async.commit_group;" ::: "memory");
}
__device__ __forceinline__ void cp_wait2(){
    asm volatile("cp.async.wait_group 2;" ::: "memory");
}

// modes: 0 C=v ; 1 Ch=half(relu v) ; 2 C=v & C2=relu ; 3 C=relu(aux)*sigmoid(v)
__device__ __forceinline__ void emit(float v, size_t idx,
                                     float* C, float* C2, __half* Ch,
                                     const float* aux, int mode){
    if(mode == 0)      C[idx] = v;
    else if(mode == 1) Ch[idx] = __float2half_rn(fmaxf(v, 0.f));
    else if(mode == 2){ C[idx] = v; C2[idx] = fmaxf(v, 0.f); }
    else { float s = 1.f/(1.f + __expf(-v)); C[idx] = fmaxf(aux[idx], 0.f) * s; }
}

__global__ void __launch_bounds__(256, 2)
k_hgemm(int M, int Ncol, int K,
        const __half* __restrict__ A, int lda,
        const __half* __restrict__ W, int ldw,
        const float* __restrict__ bias,
        float* __restrict__ C, int ldc,
        float* __restrict__ C2, __half* __restrict__ Ch,
        const float* __restrict__ aux, int mode)
{
    extern __shared__ unsigned char smem_raw[];

    const int tid  = threadIdx.x;
    const int lane = tid & 31;
    const int warp = tid >> 5;
    const int tg   = lane & 3;
    const int g    = lane >> 2;
    const int bm   = blockIdx.y * 128;
    const int bn   = blockIdx.x * 128;
    const int mw   = (warp >> 2) * 64;
    const int nw   = (warp & 3) * 32;

    const unsigned sAaddr = (unsigned)__cvta_generic_to_shared(smem_raw);
    const unsigned sBaddr = sAaddr + STAGES*TWB;

    // copy coords: 2 x 16B chunks each for A and B per thread
    // tile = 128 rows x 32 halfs = 512 x 16B chunks; 256 threads -> 2 each
    int cR[2], cK8[2];
    #pragma unroll
    for(int i=0;i<2;i++){
        int u = i*256 + tid;
        cR[i] = u >> 2; cK8[i] = (u & 3) << 3;   // half offset 0/8/16/24
    }

    auto issue = [&](int kc, int buf){           // kc = chunk index (32 halfs each)
        const int k0 = kc * 32;
        #pragma unroll
        for(int i=0;i<2;i++){
            unsigned doff = (unsigned)(buf*TWB + cR[i]*(RSH*2) + cK8[i]*2);
            int gm = bm + cR[i];
            const __half* srcA = A + (size_t)(gm < M ? gm : 0)*lda + k0 + cK8[i];
            cp16(sAaddr + doff, srcA, gm < M ? 16 : 0);
            const __half* srcB = W + (size_t)(bn + cR[i])*ldw + k0 + cK8[i];
            cp16(sBaddr + doff, srcB, 16);
        }
        cp_commit();
    };

    // ldmatrix addressing: lanes 0-15 -> rows at half-col 0, 16-31 -> half-col 8
    const int lr  = lane & 15;
    const int lc8 = (lane >> 4) << 3;
    unsigned aOff[4], bOff[2];
    #pragma unroll
    for(int mi=0;mi<4;mi++)  aOff[mi]  = (unsigned)(((mw + mi*16 + lr)*RSH + lc8) * 2);
    #pragma unroll
    for(int ni2=0;ni2<2;ni2++) bOff[ni2] = (unsigned)(((nw + ni2*16 + lr)*RSH + lc8) * 2);

    float acc[4][4][4];
    #pragma unroll
    for(int mi=0;mi<4;mi++)
        #pragma unroll
        for(int ni=0;ni<4;ni++)
            #pragma unroll
            for(int t=0;t<4;t++) acc[mi][ni][t] = 0.f;

    const int NC = K / 32;
    issue(0, 0); issue(1, 1); issue(2, 2);

    int buf = 0;
    for(int c=0; c<NC; c++){
        cp_wait2();
        __syncthreads();

        if (c + 3 < NC) issue(c + 3, (buf + 3) & 3);
        else            cp_commit();

        const unsigned aBase = sAaddr + (unsigned)(buf*TWB);
        const unsigned bBase = sBaddr + (unsigned)(buf*TWB);
        #pragma unroll
        for(int ks=0;ks<32;ks+=16){
            unsigned af[4][4], bf[4][2];
            #pragma unroll
            for(int mi=0;mi<4;mi++)
                ldsm4(af[mi][0], af[mi][1], af[mi][2], af[mi][3],
                      aBase + aOff[mi] + (unsigned)(ks*2));
            #pragma unroll
            for(int ni2=0;ni2<2;ni2++){
                unsigned r0,r1,r2,r3;
                ldsm4(r0, r1, r2, r3, bBase + bOff[ni2] + (unsigned)(ks*2));
                bf[ni2*2+0][0] = r0; bf[ni2*2+0][1] = r2;
                bf[ni2*2+1][0] = r1; bf[ni2*2+1][1] = r3;
            }
            #pragma unroll
            for(int mi=0;mi<4;mi++)
                #pragma unroll
                for(int ni=0;ni<4;ni++)
                    mma_f16(acc[mi][ni], af[mi], bf[ni]);
        }
        buf = (buf + 1) & 3;
    }

    // ---- epilogue
    #pragma unroll
    for(int mi=0;mi<4;mi++){
        int row0 = bm + mw + mi*16 + g;
        int row1 = row0 + 8;
        #pragma unroll
        for(int ni=0;ni<4;ni++){
            int col = bn + nw + ni*8 + tg*2;
            float b0 = bias ? bias[col]   : 0.f;
            float b1 = bias ? bias[col+1] : 0.f;
            if(row0 < M){
                size_t i0 = (size_t)row0*ldc + col;
                emit(acc[mi][ni][0] + b0, i0,   C, C2, Ch, aux, mode);
                emit(acc[mi][ni][1] + b1, i0+1, C, C2, Ch, aux, mode);
            }
            if(row1 < M){
                size_t i1 = (size_t)row1*ldc + col;
                emit(acc[mi][ni][2] + b0, i1,   C, C2, Ch, aux, mode);
                emit(acc[mi][ni][3] + b1, i1+1, C, C2, Ch, aux, mode);
            }
        }
    }
}

// ---------------- combine: h = relu(Xa[row] + EB + EC[rev] + Xd[col] + be1)
// output packed to fp16 (feeds the next GEMM)
__global__ void k_combine(const int* __restrict__ ei,
                          const float* __restrict__ be1, int E){
    long long gid = (long long)blockIdx.x*blockDim.x + threadIdx.x;
    if(gid >= (long long)E*192) return;
    int e = (int)(gid/192);
    int q = (int)(gid%192);
    int j = q*4;
    int r  = ei[e], c = ei[E+e], rv = g_rev[e];
    float4 v  = *(const float4*)(g_EB  + (size_t)e*768 + j);
    float4 xa = *(const float4*)(g_Xa  + (size_t)r*768 + j);
    float4 xd = *(const float4*)(g_Xd  + (size_t)c*768 + j);
    float4 b  = *(const float4*)(be1 + j);
    float4 o;
    o.x = v.x + xa.x + xd.x + b.x;
    o.y = v.y + xa.y + xd.y + b.y;
    o.z = v.z + xa.z + xd.z + b.z;
    o.w = v.w + xa.w + xd.w + b.w;
    if(rv >= 0){
        float4 ec = *(const float4*)(g_EC + (size_t)rv*768 + j);
        o.x += ec.x; o.y += ec.y; o.z += ec.z; o.w += ec.w;
    }
    __half2 h0 = __floats2half2_rn(fmaxf(o.x,0.f), fmaxf(o.y,0.f));
    __half2 h1 = __floats2half2_rn(fmaxf(o.z,0.f), fmaxf(o.w,0.f));
    *(uint2*)(g_hbuf + (size_t)e*768 + j) = make_uint2(*(unsigned*)&h0, *(unsigned*)&h1);
}

// ---------------- fused attention MLP + softmax + weighted + scatter-max
__global__ void __launch_bounds__(256)
k_attn(const int* __restrict__ ei,
       const float* __restrict__ Wa1, const float* __restrict__ ba1,
       const float* __restrict__ Wa2, const float* __restrict__ ba2,
       float* __restrict__ out_prob, int E)
{
    __shared__ float4 sW1[1024];
    __shared__ float4 sW2[512];
    __shared__ float  sb1[64], sb2[32];
    for(int i=threadIdx.x;i<1024;i+=256) sW1[i] = ((const float4*)Wa1)[i];
    for(int i=threadIdx.x;i<512; i+=256) sW2[i] = ((const float4*)Wa2)[i];
    if(threadIdx.x < 64) sb1[threadIdx.x] = ba1[threadIdx.x];
    if(threadIdx.x < 32) sb2[threadIdx.x] = ba2[threadIdx.x];
    __syncthreads();

    long long gid = (long long)blockIdx.x*256 + threadIdx.x;
    if(gid >= (long long)E*8) return;
    int e = (int)(gid >> 3);
    int h = (int)(gid & 7);
    int r = ei[e], c = ei[E+e];

    float ain[64];
    const float* qrow = g_Qn + (size_t)r*256 + h;
    const float* krow = g_Ke + (size_t)e*256 + h;
    #pragma unroll
    for(int i=0;i<32;i++) ain[i]    = qrow[i*8];
    #pragma unroll
    for(int i=0;i<32;i++) ain[32+i] = krow[i*8];

    float att[32];
    #pragma unroll
    for(int p=0;p<32;p++) att[p] = sb2[p];

    #pragma unroll 1
    for(int o4=0;o4<16;o4++){
        float a1v[4];
        #pragma unroll
        for(int s=0;s<4;s++){
            int o = o4*4 + s;
            float a = sb1[o];
            #pragma unroll
            for(int c4=0;c4<16;c4++){
                float4 w = sW1[o*16 + c4];
                a += w.x*ain[c4*4+0] + w.y*ain[c4*4+1]
                   + w.z*ain[c4*4+2] + w.w*ain[c4*4+3];
            }
            a1v[s] = fmaxf(a, 0.f);
        }
        #pragma unroll
        for(int p=0;p<32;p++){
            float4 w = sW2[p*16 + o4];
            att[p] += w.x*a1v[0] + w.y*a1v[1] + w.z*a1v[2] + w.w*a1v[3];
        }
    }

    const float invT = 0.17677669529663687f;
    float mx = att[0];
    #pragma unroll
    for(int p=1;p<32;p++) mx = fmaxf(mx, att[p]);
    float sum = 0.f;
    #pragma unroll
    for(int p=0;p<32;p++){ att[p] = __expf((att[p]-mx)*invT); sum += att[p]; }
    float inv = 1.f/sum;

    float* pp = out_prob + (size_t)e*256 + h;
    const float* vrow = g_Vn + (size_t)c*256 + h;
    int* ar = g_aggI + r*256 + h;
    #pragma unroll
    for(int p=0;p<32;p++){
        float pr = att[p]*inv;
        pp[p*8] = pr;
        float w = pr * vrow[p*8];
        atomicMax(ar + p*8, f2oi(w));
    }
}

// ---------------- small elementwise kernels ----------------
__global__ void k_agg_final(int N){
    int i = blockIdx.x*blockDim.x + threadIdx.x;
    if(i >= N*256) return;
    float v = oi2f(g_aggI[i]);
    g_agg[i] = isfinite(v) ? v : 0.f;
}

__global__ void k_concat(const float* __restrict__ x, int N){
    int i = blockIdx.x*blockDim.x + threadIdx.x;
    if(i >= N*512) return;
    int n = i >> 9, j = i & 511;
    float v = (j < 256) ? x[(size_t)n*256 + j] : g_agg[(size_t)n*256 + j - 256];
    g_cat[i] = __float2half_rn(v);
}

__global__ void k_counts(const int* __restrict__ ei, int E){
    int e = blockIdx.x*blockDim.x + threadIdx.x;
    if(e >= E) return;
    atomicAdd(&g_ocnt[ei[e]],   1);
    atomicAdd(&g_icnt[ei[E+e]], 1);
}

__global__ void k_twin_scatter(const int* __restrict__ ei, int E){
    long long gid = (long long)blockIdx.x*blockDim.x + threadIdx.x;
    if(gid >= (long long)E*64) return;
    int e  = (int)(gid >> 6);
    int j4 = (int)(gid & 63);
    int r = ei[e], c = ei[E+e];
    float4 u = *(const float4*)(g_upe + (size_t)e*256 + j4*4);
    int base = j4*4;
    atomicAdd(&g_osum[r*256+base+0], u.x);
    atomicAdd(&g_osum[r*256+base+1], u.y);
    atomicAdd(&g_osum[r*256+base+2], u.z);
    atomicAdd(&g_osum[r*256+base+3], u.w);
    atomicAdd(&g_isum[c*256+base+0], u.x);
    atomicAdd(&g_isum[c*256+base+1], u.y);
    atomicAdd(&g_isum[c*256+base+2], u.z);
    atomicAdd(&g_isum[c*256+base+3], u.w);
}

__global__ void k_twin_final(int N){
    int i = blockIdx.x*blockDim.x + threadIdx.x;
    if(i >= N*512) return;
    int n = i >> 9, j = i & 511;
    float v;
    if(j < 256) v = g_osum[n*256 + j]       / fmaxf((float)g_ocnt[n], 1.f);
    else        v = g_isum[n*256 + j - 256] / fmaxf((float)g_icnt[n], 1.f);
    g_twin[i] = __float2half_rn(v);
}

// ---------------- launcher ----------------
extern "C" void kernel_launch(void* const* d_in, const int* in_sizes, int n_in,
                              void* d_out, int out_size)
{
    const float* x   = (const float*)d_in[0];
    const float* ea  = (const float*)d_in[1];
    const float* Wq  = (const float*)d_in[2];
    const float* bq  = (const float*)d_in[3];
    const float* Wk  = (const float*)d_in[4];
    const float* bk  = (const float*)d_in[5];
    const float* Wv  = (const float*)d_in[6];
    const float* bv  = (const float*)d_in[7];
    const float* We1 = (const float*)d_in[8];
    const float* be1 = (const float*)d_in[9];
    const float* We2 = (const float*)d_in[10];
    const float* be2 = (const float*)d_in[11];
    const float* Wea = (const float*)d_in[12];
    const float* bea = (const float*)d_in[13];
    const float* Wn1 = (const float*)d_in[14];
    const float* bn1 = (const float*)d_in[15];
    const float* Wn2 = (const float*)d_in[16];
    const float* bn2 = (const float*)d_in[17];
    const float* Wa1 = (const float*)d_in[18];
    const float* ba1 = (const float*)d_in[19];
    const float* Wa2 = (const float*)d_in[20];
    const float* ba2 = (const float*)d_in[21];
    const int*   ei  = (const int*)  d_in[22];

    const int N = in_sizes[0]/256;
    const int E = in_sizes[1]/256;

    float* out      = (float*)d_out;
    float* out_node = out;
    float* out_edge = out + (size_t)N*256;
    float* out_prob = out_edge + (size_t)E*256;

    void* p;
    #define GSYMF(v, s) float* v; cudaGetSymbolAddress(&p, s); v = (float*)p;
    #define GSYMH(v, s) __half* v; cudaGetSymbolAddress(&p, s); v = (__half*)p;
    GSYMF(pXa,  g_Xa)  GSYMF(pXd,  g_Xd)  GSYMF(pEB, g_EB) GSYMF(pEC, g_EC)
    GSYMF(pUPE, g_upe)
    GSYMF(pQ,   g_Qn)  GSYMF(pV,   g_Vn)  GSYMF(pK,  g_Ke)
    GSYMF(pUpn, g_upn)
    GSYMH(pH,   g_hbuf)
    GSYMH(pCat, g_cat) GSYMH(pHn, g_hn)  GSYMH(pTwin, g_twin)
    GSYMH(pXr,  g_xr)  GSYMH(pEar, g_ear)
    GSYMH(pWe1h, g_We1h) GSYMH(pWe2h, g_We2h)
    GSYMH(pWqh, g_Wqh) GSYMH(pWkh, g_Wkh) GSYMH(pWvh, g_Wvh)
    GSYMH(pWn1h, g_Wn1h) GSYMH(pWn2h, g_Wn2h) GSYMH(pWeah, g_Weah)
    #undef GSYMF
    #undef GSYMH

    cudaFuncSetAttribute(k_hgemm, cudaFuncAttributeMaxDynamicSharedMemorySize, SMEM_BYTES);

    // convert GEMM operands to fp16
    auto H = [&](const float* src, __half* dst, int n){
        k_tohalf<<<(n/4 + 255)/256, 256>>>((const float4*)src, (uint2*)dst, n/4);
    };
    H(x,   pXr,   N*256);
    H(ea,  pEar,  E*256);
    H(We1, pWe1h, 768*1024);
    H(We2, pWe2h, 256*768);
    H(Wq,  pWqh,  256*256);
    H(Wk,  pWkh,  256*256);
    H(Wv,  pWvh,  256*256);
    H(Wn1, pWn1h, 512*512);
    H(Wn2, pWn2h, 256*512);
    H(Wea, pWeah, 256*512);

    k_init<<<(NN*256+255)/256, 256>>>(N);
    k_hash_insert<<<(E+255)/256, 256>>>(ei, E, N);
    k_rev<<<(E+255)/256, 256>>>(ei, E, N);

    auto GEMM = [&](int M, int Nc, int K, const __half* A, int lda,
                    const __half* W, int ldw, const float* bias,
                    float* C, int ldc, float* C2, __half* Ch,
                    const float* aux, int mode){
        dim3 g(Nc/128, (M+127)/128);
        k_hgemm<<<g, 256, SMEM_BYTES>>>(M, Nc, K, A, lda, W, ldw, bias,
                                        C, ldc, C2, Ch, aux, mode);
    };

    // edge-update MLP, factored by We1 column blocks
    GEMM(N, 768, 256, pXr,  256, pWe1h + 0,   1024, nullptr, pXa, 768, nullptr, nullptr, nullptr, 0);
    GEMM(N, 768, 256, pXr,  256, pWe1h + 768, 1024, nullptr, pXd, 768, nullptr, nullptr, nullptr, 0);
    GEMM(E, 768, 256, pEar, 256, pWe1h + 256, 1024, nullptr, pEB, 768, nullptr, nullptr, nullptr, 0);
    GEMM(E, 768, 256, pEar, 256, pWe1h + 512, 1024, nullptr, pEC, 768, nullptr, nullptr, nullptr, 0);
    k_combine<<<(int)(((long long)E*192 + 255)/256), 256>>>(ei, be1, E);
    GEMM(E, 256, 768, pH, 768, pWe2h, 768, be2, pUPE, 256, out_edge, nullptr, nullptr, 2);

    // q/v per node, k per edge
    GEMM(N, 256, 256, pXr,  256, pWqh, 256, bq, pQ, 256, nullptr, nullptr, nullptr, 0);
    GEMM(N, 256, 256, pXr,  256, pWvh, 256, bv, pV, 256, nullptr, nullptr, nullptr, 0);
    GEMM(E, 256, 256, pEar, 256, pWkh, 256, bk, pK, 256, nullptr, nullptr, nullptr, 0);

    // attention + scatter-max aggregation
    k_attn<<<(int)(((long long)E*8 + 255)/256), 256>>>(ei, Wa1, ba1, Wa2, ba2, out_prob, E);
    k_agg_final<<<(N*256+255)/256, 256>>>(N);

    // node update MLP
    k_concat<<<(N*512+255)/256, 256>>>(x, N);
    GEMM(N, 512, 512, pCat, 512, pWn1h, 512, bn1, nullptr, 512, nullptr, pHn, nullptr, 1);
    GEMM(N, 256, 512, pHn,  512, pWn2h, 512, bn2, pUpn, 256, nullptr, nullptr, nullptr, 0);

    // twin aggregation + gated output
    k_counts<<<(E+255)/256, 256>>>(ei, E);
    k_twin_scatter<<<(int)(((long long)E*64 + 255)/256), 256>>>(ei, E);
    k_twin_final<<<(N*512+255)/256, 256>>>(N);
    GEMM(N, 256, 512, pTwin, 512, pWeah, 512, bea, out_node, 256, nullptr, nullptr, pUpn, 3);
}